// round 1
// baseline (speedup 1.0000x reference)
#include <cuda_runtime.h>
#include <cstdint>

#define N_NODES 8192
#define D       512
#define CAP     256   // max neighbors per row (deg mean ~32, std ~5.7; 256 is untouchable)

// ---- scratch (device globals; no allocation allowed) ----
__device__ int   g_csr[N_NODES * CAP];
__device__ int   g_cnt[N_NODES];
__device__ float g_dis[N_NODES];
__device__ float g_xs[N_NODES * D];
__device__ float g_h[N_NODES * D];

// =====================================================================
// Kernel 1: scan dense A once -> per-row CSR + symmetric-norm scale
// =====================================================================
__global__ __launch_bounds__(256) void build_csr_kernel(const float* __restrict__ A) {
    int row = blockIdx.x;
    __shared__ int s_cnt;
    if (threadIdx.x == 0) s_cnt = 0;
    __syncthreads();

    const float4* Arow = reinterpret_cast<const float4*>(A + (size_t)row * N_NODES);
    int* csr_row = g_csr + row * CAP;

    for (int v = threadIdx.x; v < N_NODES / 4; v += 256) {
        float4 f = Arow[v];
        int base = v * 4;
        if (f.x != 0.0f) { int s = atomicAdd(&s_cnt, 1); if (s < CAP) csr_row[s] = base;     }
        if (f.y != 0.0f) { int s = atomicAdd(&s_cnt, 1); if (s < CAP) csr_row[s] = base + 1; }
        if (f.z != 0.0f) { int s = atomicAdd(&s_cnt, 1); if (s < CAP) csr_row[s] = base + 2; }
        if (f.w != 0.0f) { int s = atomicAdd(&s_cnt, 1); if (s < CAP) csr_row[s] = base + 3; }
    }
    __syncthreads();
    if (threadIdx.x == 0) {
        int c = s_cnt;
        g_cnt[row] = (c < CAP) ? c : CAP;
        // A_tilde = A + I  ->  deg = nnz(row) + 1  (diag of A is zero by construction)
        g_dis[row] = rsqrtf((float)(c + 1));
    }
}

// =====================================================================
// Kernel 2: xs[j,:] = dis[j] * x[j,:]
// =====================================================================
__global__ __launch_bounds__(256) void scale_x_kernel(const float* __restrict__ x) {
    int idx = blockIdx.x * 256 + threadIdx.x;          // float4 index
    float4 v = reinterpret_cast<const float4*>(x)[idx];
    float d = g_dis[idx >> 7];                          // D/4 = 128 float4 per row
    v.x *= d; v.y *= d; v.z *= d; v.w *= d;
    reinterpret_cast<float4*>(g_xs)[idx] = v;
}

// =====================================================================
// Kernel 3: h[i,:] = dis[i] * ( xs[i,:] + sum_{j in adj(i)} xs[j,:] )
// =====================================================================
__global__ __launch_bounds__(128) void aggregate_kernel() {
    int row = blockIdx.x;
    __shared__ int s_nbr[CAP];
    __shared__ int s_cnt_sh;
    if (threadIdx.x == 0) s_cnt_sh = g_cnt[row];
    __syncthreads();
    int cnt = s_cnt_sh;
    for (int e = threadIdx.x; e < cnt; e += 128) s_nbr[e] = g_csr[row * CAP + e];
    __syncthreads();

    const float4* xs4 = reinterpret_cast<const float4*>(g_xs);
    const int c = threadIdx.x;                          // owns cols [4c, 4c+4)
    float4 acc = xs4[row * (D / 4) + c];                // self term (already dis[i]*x[i])

    int e = 0;
    for (; e + 4 <= cnt; e += 4) {                      // 4-wide for MLP
        int j0 = s_nbr[e], j1 = s_nbr[e + 1], j2 = s_nbr[e + 2], j3 = s_nbr[e + 3];
        float4 v0 = xs4[j0 * (D / 4) + c];
        float4 v1 = xs4[j1 * (D / 4) + c];
        float4 v2 = xs4[j2 * (D / 4) + c];
        float4 v3 = xs4[j3 * (D / 4) + c];
        acc.x += (v0.x + v1.x) + (v2.x + v3.x);
        acc.y += (v0.y + v1.y) + (v2.y + v3.y);
        acc.z += (v0.z + v1.z) + (v2.z + v3.z);
        acc.w += (v0.w + v1.w) + (v2.w + v3.w);
    }
    for (; e < cnt; e++) {
        int j = s_nbr[e];
        float4 v = xs4[j * (D / 4) + c];
        acc.x += v.x; acc.y += v.y; acc.z += v.z; acc.w += v.w;
    }
    float d = g_dis[row];
    acc.x *= d; acc.y *= d; acc.z *= d; acc.w *= d;
    reinterpret_cast<float4*>(g_h)[row * (D / 4) + c] = acc;
}

// =====================================================================
// Kernel 4: out = relu(h @ W^T + b)   -- tf32 mma.sync, 128x64x16 tiles
// =====================================================================
#define BM 128
#define BN 64
#define BK 16

__device__ __forceinline__ uint32_t f2tf32(float f) {
    uint32_t u;
    asm("cvt.rna.tf32.f32 %0, %1;" : "=r"(u) : "f"(f));
    return u;
}

__device__ __forceinline__ void mma_tf32(float* c, const uint32_t* a, const uint32_t* b) {
    asm volatile(
        "mma.sync.aligned.m16n8k8.row.col.f32.tf32.tf32.f32 "
        "{%0,%1,%2,%3}, {%4,%5,%6,%7}, {%8,%9}, {%0,%1,%2,%3};\n"
        : "+f"(c[0]), "+f"(c[1]), "+f"(c[2]), "+f"(c[3])
        : "r"(a[0]), "r"(a[1]), "r"(a[2]), "r"(a[3]), "r"(b[0]), "r"(b[1]));
}

__global__ __launch_bounds__(256) void gemm_kernel(const float* __restrict__ W,
                                                   const float* __restrict__ bias,
                                                   float* __restrict__ out) {
    __shared__ float sA[BM][BK + 1];
    __shared__ float sB[BN][BK + 1];

    const int m0 = blockIdx.y * BM;
    const int n0 = blockIdx.x * BN;
    const int tid = threadIdx.x;
    const int wid = tid >> 5, lane = tid & 31;
    const int g = lane >> 2, t = lane & 3;
    const int wm0 = (wid & 3) * 32;   // warp grid 4 (M) x 2 (N), warp tile 32x32
    const int wn0 = (wid >> 2) * 32;

    const int lr = tid >> 2;          // 0..63
    const int lc = (tid & 3) * 4;     // 0,4,8,12

    float acc[2][4][4];
    #pragma unroll
    for (int mt = 0; mt < 2; mt++)
        #pragma unroll
        for (int nt = 0; nt < 4; nt++)
            #pragma unroll
            for (int r = 0; r < 4; r++) acc[mt][nt][r] = 0.0f;

    for (int k0 = 0; k0 < D; k0 += BK) {
        float4 a0v = *reinterpret_cast<const float4*>(&g_h[(size_t)(m0 + lr) * D + k0 + lc]);
        float4 a1v = *reinterpret_cast<const float4*>(&g_h[(size_t)(m0 + lr + 64) * D + k0 + lc]);
        float4 bv  = *reinterpret_cast<const float4*>(&W[(size_t)(n0 + lr) * D + k0 + lc]);
        __syncthreads();
        sA[lr][lc + 0] = a0v.x; sA[lr][lc + 1] = a0v.y; sA[lr][lc + 2] = a0v.z; sA[lr][lc + 3] = a0v.w;
        sA[lr + 64][lc + 0] = a1v.x; sA[lr + 64][lc + 1] = a1v.y; sA[lr + 64][lc + 2] = a1v.z; sA[lr + 64][lc + 3] = a1v.w;
        sB[lr][lc + 0] = bv.x; sB[lr][lc + 1] = bv.y; sB[lr][lc + 2] = bv.z; sB[lr][lc + 3] = bv.w;
        __syncthreads();

        #pragma unroll
        for (int kt = 0; kt < 2; kt++) {
            const int kk = kt * 8;
            uint32_t af[2][4], bf[4][2];
            #pragma unroll
            for (int mt = 0; mt < 2; mt++) {
                const int r = wm0 + mt * 16;
                af[mt][0] = f2tf32(sA[r + g][kk + t]);
                af[mt][1] = f2tf32(sA[r + g + 8][kk + t]);
                af[mt][2] = f2tf32(sA[r + g][kk + t + 4]);
                af[mt][3] = f2tf32(sA[r + g + 8][kk + t + 4]);
            }
            #pragma unroll
            for (int nt = 0; nt < 4; nt++) {
                const int cn = wn0 + nt * 8;
                bf[nt][0] = f2tf32(sB[cn + g][kk + t]);
                bf[nt][1] = f2tf32(sB[cn + g][kk + t + 4]);
            }
            #pragma unroll
            for (int mt = 0; mt < 2; mt++)
                #pragma unroll
                for (int nt = 0; nt < 4; nt++)
                    mma_tf32(acc[mt][nt], af[mt], bf[nt]);
        }
    }

    // epilogue: bias + relu
    #pragma unroll
    for (int mt = 0; mt < 2; mt++) {
        #pragma unroll
        for (int nt = 0; nt < 4; nt++) {
            const int r0 = m0 + wm0 + mt * 16 + g;
            const int cc = n0 + wn0 + nt * 8 + t * 2;
            const float b0 = bias[cc], b1 = bias[cc + 1];
            float v;
            v = acc[mt][nt][0] + b0; out[(size_t)r0 * D + cc]           = v > 0.0f ? v : 0.0f;
            v = acc[mt][nt][1] + b1; out[(size_t)r0 * D + cc + 1]       = v > 0.0f ? v : 0.0f;
            v = acc[mt][nt][2] + b0; out[(size_t)(r0 + 8) * D + cc]     = v > 0.0f ? v : 0.0f;
            v = acc[mt][nt][3] + b1; out[(size_t)(r0 + 8) * D + cc + 1] = v > 0.0f ? v : 0.0f;
        }
    }
}

// =====================================================================
extern "C" void kernel_launch(void* const* d_in, const int* in_sizes, int n_in,
                              void* d_out, int out_size) {
    // identify inputs by element count (robust to metadata ordering)
    const float *x = nullptr, *A = nullptr, *W = nullptr, *b = nullptr;
    for (int i = 0; i < n_in; i++) {
        switch (in_sizes[i]) {
            case N_NODES * D:                 x = (const float*)d_in[i]; break;
            case 67108864 /* 8192*8192 */:    A = (const float*)d_in[i]; break;
            case D * D:                       W = (const float*)d_in[i]; break;
            case D:                           b = (const float*)d_in[i]; break;
        }
    }
    float* out = (float*)d_out;

    build_csr_kernel<<<N_NODES, 256>>>(A);
    scale_x_kernel<<<(N_NODES * D / 4) / 256, 256>>>(x);
    aggregate_kernel<<<N_NODES, 128>>>();
    dim3 grid(D / BN, N_NODES / BM);
    gemm_kernel<<<grid, 256>>>(W, b, out);
}